// round 17
// baseline (speedup 1.0000x reference)
#include <cuda_runtime.h>
#include <cuda_bf16.h>
#include <mma.h>

using namespace nvcuda;

#define NN 100000
#define NE 3200000
#define CH 128
#define NB    ((NN + 255) / 256)   // 391 node blocks
#define SCB   (NE / 4 / 256)       // 3125 edge blocks (4 edges/thread)
#define NT32  (NN / 32)            // 3125 row tiles of 32 (NN % 32 == 0)
#define GMB   782                  // gemm blocks (grid-stride over NT32)
#define WPAD  136                  // W smem row stride (floats): 544 B = 17*32B
#define STP   36                   // staging row stride (floats)
#define GEMM_SMEM (128 * WPAD * 4) // 69632 B dynamic

// Scratch (static device globals: allocation-free per harness rules).
// g_cnt invariant: zero at entry of every kernel_launch call (static init
// zeroes it; k_aggr re-zeroes it every call).
__device__ int   g_cnt[NN];               // in-degree (excl. self loop)
__device__ int   g_off[NN];               // CSR offsets (exclusive scan of cnt)
__device__ int   g_cur[NN];               // scatter cursors
__device__ int   g_csr[NE];               // source ids grouped by target
__device__ float g_dinv[NN];
__device__ float g_xws[(size_t)NN * CH];  // dinv[i] * (X @ W), fp32, 51.2 MB

// ---------------------------------------------------------------------------
// Launch 0: degree histogram, 4 edges per thread (int32 indices).
// ---------------------------------------------------------------------------
__global__ void __launch_bounds__(256) k_count(const int4* __restrict__ cols4) {
    int t = blockIdx.x * 256 + threadIdx.x;
    if (t < NE / 4) {
        int4 v = __ldg(&cols4[t]);
        atomicAdd(&g_cnt[v.x], 1);
        atomicAdd(&g_cnt[v.y], 1);
        atomicAdd(&g_cnt[v.z], 1);
        atomicAdd(&g_cnt[v.w], 1);
    }
}

// ---------------------------------------------------------------------------
// Launch 1: single-kernel scan (global prefix via strided re-sum) -> off/cur/dinv.
// ---------------------------------------------------------------------------
__global__ void __launch_bounds__(256) k_fill() {
    __shared__ int wred[8];
    __shared__ int wpre[8];
    __shared__ int s_block_prefix;
    const int tid  = threadIdx.x;
    const int lane = tid & 31, wid = tid >> 5;
    const int base = blockIdx.x * 256;

    int s = 0;
    for (int i = tid; i < base; i += 256) s += g_cnt[i];
#pragma unroll
    for (int o = 16; o > 0; o >>= 1) s += __shfl_down_sync(0xFFFFFFFFu, s, o);
    if (lane == 0) wred[wid] = s;
    __syncthreads();
    if (wid == 0) {
        int t = (lane < 8) ? wred[lane] : 0;
#pragma unroll
        for (int o = 4; o > 0; o >>= 1) t += __shfl_down_sync(0xFFFFFFFFu, t, o);
        if (lane == 0) s_block_prefix = t;
    }
    __syncthreads();

    const int i = base + tid;
    int c = (i < NN) ? g_cnt[i] : 0;
    int v = c;
#pragma unroll
    for (int o = 1; o < 32; o <<= 1) {
        int u = __shfl_up_sync(0xFFFFFFFFu, v, o);
        if (lane >= o) v += u;
    }
    if (lane == 31) wpre[wid] = v;
    __syncthreads();
    if (wid == 0 && lane < 8) {
        int w = wpre[lane];
#pragma unroll
        for (int o = 1; o < 8; o <<= 1) {
            int u = __shfl_up_sync(0x000000FFu, w, o);
            if (lane >= o) w += u;
        }
        wpre[lane] = w;
    }
    __syncthreads();

    if (i < NN) {
        int excl = v - c + (wid > 0 ? wpre[wid - 1] : 0) + s_block_prefix;
        g_off[i]  = excl;
        g_cur[i]  = excl;
        g_dinv[i] = rsqrtf(1.0f + (float)c);
    }
}

// ---------------------------------------------------------------------------
// Launch 2: CSR scatter, 4 edges per thread.
// ---------------------------------------------------------------------------
__global__ void __launch_bounds__(256) k_scatter(const int4* __restrict__ rows4,
                                                 const int4* __restrict__ cols4) {
    int t = blockIdx.x * 256 + threadIdx.x;
    int4 r = __ldg(&rows4[t]);
    int4 c = __ldg(&cols4[t]);
    g_csr[atomicAdd(&g_cur[c.x], 1)] = r.x;
    g_csr[atomicAdd(&g_cur[c.y], 1)] = r.y;
    g_csr[atomicAdd(&g_cur[c.z], 1)] = r.z;
    g_csr[atomicAdd(&g_cur[c.w], 1)] = r.w;
}

// ---------------------------------------------------------------------------
// Launch 3 (ncu target): tf32 GEMM, W staged in smem PRE-CONVERTED to tf32
// (no F2F on the B path in the mainloop). Warp tile = 16 rows x 32 cols
// (2 accumulator fragments -> ~50 regs). Block = 8 warps = 32 rows x 128 cols,
// grid-stride over 32-row tiles. Epilogue folds dinv[row] via per-warp
// padded smem staging. One __syncthreads (after W staging).
// ---------------------------------------------------------------------------
__global__ void __launch_bounds__(256) k_gemm(const float* __restrict__ X,
                                              const float* __restrict__ W) {
    extern __shared__ float sW[];            // 128 x WPAD (tf32 values)
    __shared__ float stg[8][16 * STP];       // per-warp 16 x 32 staging

    const int tid  = threadIdx.x;
    const int lane = tid & 31;
    const int wid  = tid >> 5;
    const int rg   = wid >> 2;               // row group: 0 or 1
    const int cg   = wid & 3;                // col group: 0..3
    const int n0   = cg * 32;

    // stage W, converting to tf32 once
    for (int i = tid; i < 128 * 32; i += 256) {
        int row = i >> 5, c4 = (i & 31) * 4;
        float4 v = *(const float4*)&W[row * CH + c4];
        sW[row * WPAD + c4 + 0] = wmma::__float_to_tf32(v.x);
        sW[row * WPAD + c4 + 1] = wmma::__float_to_tf32(v.y);
        sW[row * WPAD + c4 + 2] = wmma::__float_to_tf32(v.z);
        sW[row * WPAD + c4 + 3] = wmma::__float_to_tf32(v.w);
    }
    __syncthreads();

    wmma::fragment<wmma::matrix_a, 16, 16, 8, wmma::precision::tf32, wmma::row_major> a;
    wmma::fragment<wmma::matrix_b, 16, 16, 8, wmma::precision::tf32, wmma::row_major> b0, b1;
    wmma::fragment<wmma::accumulator, 16, 16, 8, float> c0, c1;

    for (int tile = blockIdx.x; tile < NT32; tile += GMB) {
        const int row0 = tile * 32 + rg * 16;
        wmma::fill_fragment(c0, 0.0f);
        wmma::fill_fragment(c1, 0.0f);

#pragma unroll
        for (int k = 0; k < 16; k++) {
            wmma::load_matrix_sync(a, X + (size_t)row0 * CH + k * 8, CH);
#pragma unroll
            for (int i = 0; i < a.num_elements; i++)
                a.x[i] = wmma::__float_to_tf32(a.x[i]);
            wmma::load_matrix_sync(b0, &sW[(k * 8) * WPAD + n0], WPAD);
            wmma::load_matrix_sync(b1, &sW[(k * 8) * WPAD + n0 + 16], WPAD);
            wmma::mma_sync(c0, a, b0, c0);
            wmma::mma_sync(c1, a, b1, c1);
        }

        // epilogue: stage 16x32, scale rows by dinv, store
        wmma::store_matrix_sync(&stg[wid][0],  c0, STP, wmma::mem_row_major);
        wmma::store_matrix_sync(&stg[wid][16], c1, STP, wmma::mem_row_major);
        __syncwarp();
#pragma unroll
        for (int t = 0; t < 4; t++) {
            int fid = lane + t * 32;         // 0..127: 16 rows x 8 float4s
            int r   = fid >> 3;
            int q   = (fid & 7) * 4;
            int grow = row0 + r;
            float s  = g_dinv[grow];
            float4 v = *(const float4*)&stg[wid][r * STP + q];
            float4 o = make_float4(s * v.x, s * v.y, s * v.z, s * v.w);
            *(float4*)&g_xws[(size_t)grow * CH + n0 + q] = o;
        }
        __syncwarp();
    }
}

// ---------------------------------------------------------------------------
// Launch 4: pull-mode aggregation over pre-scaled rows, warp per node.
//   out[c] = dinv[c] * (xws[c] + sum_r xws[r]) + bias
// Inner loop: 1 SHFL + 1 LDG.128 + 4 FADD per edge. Restores g_cnt = 0.
// ---------------------------------------------------------------------------
__global__ void __launch_bounds__(256) k_aggr(float* __restrict__ out,
                                              const float* __restrict__ bias) {
    int warp = (blockIdx.x * 256 + threadIdx.x) >> 5;
    int lane = threadIdx.x & 31;
    if (warp >= NN) return;
    const int c   = warp;
    const int off = g_off[c];
    const int n   = g_cnt[c];
    const float sc = g_dinv[c];

    // self-loop term (xws already carries dinv[c])
    float4 acc = *(const float4*)&g_xws[(size_t)c * CH + lane * 4];

    for (int i = 0; i < n; i += 32) {
        int chunk = n - i; if (chunk > 32) chunk = 32;
        int r = (lane < chunk) ? __ldg(&g_csr[off + i + lane]) : 0;
#pragma unroll 4
        for (int j = 0; j < chunk; j++) {
            int rj = __shfl_sync(0xFFFFFFFFu, r, j);
            float4 v = *(const float4*)&g_xws[(size_t)rj * CH + lane * 4];
            acc.x += v.x; acc.y += v.y; acc.z += v.z; acc.w += v.w;
        }
    }

    float4 b = *(const float4*)&bias[lane * 4];
    float4 o = make_float4(sc * acc.x + b.x, sc * acc.y + b.y,
                           sc * acc.z + b.z, sc * acc.w + b.w);
    *(float4*)&out[(size_t)c * CH + lane * 4] = o;

    // restore invariant for the next kernel_launch call
    if (lane == 0) g_cnt[c] = 0;
}

// ---------------------------------------------------------------------------
extern "C" void kernel_launch(void* const* d_in, const int* in_sizes, int n_in,
                              void* d_out, int out_size) {
    const float* X    = (const float*)d_in[0];
    const int*   ei   = (const int*)d_in[1];     // [2, NE] int32
    // d_in[2] = batch (unused by GCNConv)
    const float* W    = (const float*)d_in[3];
    const float* bias = (const float*)d_in[4];
    float*       out  = (float*)d_out;

    const int4* rows4 = (const int4*)ei;          // sources
    const int4* cols4 = (const int4*)(ei + NE);   // targets

    static bool s_init = false;
    if (!s_init) {
        cudaFuncSetAttribute(k_gemm, cudaFuncAttributeMaxDynamicSharedMemorySize,
                             GEMM_SMEM);
        s_init = true;
    }

    k_count<<<SCB, 256>>>(cols4);                          // launch 0
    k_fill<<<NB, 256>>>();                                 // launch 1
    k_scatter<<<SCB, 256>>>(rows4, cols4);                 // launch 2
    k_gemm<<<GMB, 256, GEMM_SMEM>>>(X, W);                 // launch 3 (ncu)
    k_aggr<<<(NN * 32 + 255) / 256, 256>>>(out, bias);     // launch 4
}